// round 1
// baseline (speedup 1.0000x reference)
#include <cuda_runtime.h>

// DynamicMaskHead fused kernel for GB300 (sm_103a).
// One block per (instance, head). Phase 1: 3-layer per-instance MLP over the
// 96x160 feature grid into shared memory. Phase 2: aligned_bilinear x2 +
// sigmoid directly to global output (float4 stores).

#define HH      96
#define WW      160
#define HW      15360      // 96*160
#define OHh     192
#define OWw     320
#define OHW     61440      // 192*320
#define NP      169        // params per instance
#define NTHREADS 256

__global__ __launch_bounds__(NTHREADS, 2)
void dmh_kernel(const float* __restrict__ feats,     // [2, 8, 96, 160]
                const float* __restrict__ p1,        // [N, 169]
                const float* __restrict__ p2,        // [N, 169]
                const float* __restrict__ loc,       // [N, 2]
                const float* __restrict__ off,       // [N, 2]
                const int*   __restrict__ imi,       // [N]
                const int*   __restrict__ fpn,       // [N]
                float*       __restrict__ out)       // [2, N, 1, 192, 320]
{
    extern __shared__ float smem[];
    float* sL = smem;          // [HW] logits tile
    float* sp = smem + HW;     // [NP] params

    const int tid  = threadIdx.x;
    const int inst = blockIdx.x;
    const int head = blockIdx.y;
    const int n_inst = gridDim.x;

    const float* params = (head == 0 ? p1 : p2) + inst * NP;
    if (tid < NP) sp[tid] = params[tid];

    const int   im      = imi[inst];
    const int   lvl     = fpn[inst];
    const float inv_soi = 1.0f / (64.0f * (float)(1 << lvl));
    float lx = loc[2 * inst + 0];
    float ly = loc[2 * inst + 1];
    if (head) {
        lx += off[2 * inst + 0] * 128.0f;
        ly += off[2 * inst + 1] * 128.0f;
    }
    __syncthreads();

    const float* fb = feats + (size_t)im * (8 * HW);

    // ---------------- Phase 1: MLP over 15360 pixels, 4 pixels/thread/iter ----
    #pragma unroll 1
    for (int it = 0; it < HW / (NTHREADS * 4); ++it) {
        const int p0  = tid * 4 + it * (NTHREADS * 4);   // multiple of 4; 160%4==0 -> same row
        const int py  = p0 / WW;
        const int px0 = p0 - py * WW;

        float xin[10][4];
        const float ry = (ly - (float)(py * 8 + 4)) * inv_soi;
        #pragma unroll
        for (int k = 0; k < 4; ++k) {
            xin[0][k] = (lx - (float)((px0 + k) * 8 + 4)) * inv_soi;
            xin[1][k] = ry;
        }
        #pragma unroll
        for (int c = 0; c < 8; ++c) {
            const float4 v = *reinterpret_cast<const float4*>(fb + c * HW + p0);
            xin[2 + c][0] = v.x; xin[2 + c][1] = v.y;
            xin[2 + c][2] = v.z; xin[2 + c][3] = v.w;
        }

        // Layer 0: [8 x 10] + bias, ReLU
        float h1[8][4];
        #pragma unroll
        for (int c = 0; c < 8; ++c) {
            const float b = sp[152 + c];
            float a0 = b, a1 = b, a2 = b, a3 = b;
            #pragma unroll
            for (int i = 0; i < 10; ++i) {
                const float w = sp[c * 10 + i];
                a0 += w * xin[i][0]; a1 += w * xin[i][1];
                a2 += w * xin[i][2]; a3 += w * xin[i][3];
            }
            h1[c][0] = fmaxf(a0, 0.f); h1[c][1] = fmaxf(a1, 0.f);
            h1[c][2] = fmaxf(a2, 0.f); h1[c][3] = fmaxf(a3, 0.f);
        }

        // Layer 1: [8 x 8] + bias, ReLU
        float h2[8][4];
        #pragma unroll
        for (int c = 0; c < 8; ++c) {
            const float b = sp[160 + c];
            float a0 = b, a1 = b, a2 = b, a3 = b;
            #pragma unroll
            for (int i = 0; i < 8; ++i) {
                const float w = sp[80 + c * 8 + i];
                a0 += w * h1[i][0]; a1 += w * h1[i][1];
                a2 += w * h1[i][2]; a3 += w * h1[i][3];
            }
            h2[c][0] = fmaxf(a0, 0.f); h2[c][1] = fmaxf(a1, 0.f);
            h2[c][2] = fmaxf(a2, 0.f); h2[c][3] = fmaxf(a3, 0.f);
        }

        // Layer 2: [1 x 8] + bias
        const float b2 = sp[168];
        float o0 = b2, o1 = b2, o2 = b2, o3 = b2;
        #pragma unroll
        for (int c = 0; c < 8; ++c) {
            const float w = sp[144 + c];
            o0 += w * h2[c][0]; o1 += w * h2[c][1];
            o2 += w * h2[c][2]; o3 += w * h2[c][3];
        }
        *reinterpret_cast<float4*>(sL + p0) = make_float4(o0, o1, o2, o3);
    }
    __syncthreads();

    // ---------------- Phase 2: aligned_bilinear x2 + sigmoid -----------------
    // Per axis (factor 2): out[0]=t[0]; out[2k+1]=t[k]; out[2k]=0.5*(t[k-1]+t[k])
    float* ob = out + ((size_t)head * n_inst + inst) * (size_t)OHW;

    #pragma unroll 1
    for (int it = 0; it < OHW / (NTHREADS * 4); ++it) {
        const int q   = tid + it * NTHREADS;    // quad index, 4 consecutive ox
        const int oy  = q / (OWw / 4);
        const int ox4 = (q - oy * (OWw / 4)) * 4;
        const int c   = ox4 >> 1;               // 0..158
        const int cm1 = (c > 0) ? c - 1 : 0;

        int r0, r1; float w0, w1;
        if (oy & 1)        { r0 = oy >> 1;       r1 = r0;      w0 = 1.0f; w1 = 0.0f; }
        else if (oy == 0)  { r0 = 0;             r1 = 0;       w0 = 1.0f; w1 = 0.0f; }
        else               { r1 = oy >> 1;       r0 = r1 - 1;  w0 = 0.5f; w1 = 0.5f; }

        const float* row0 = sL + r0 * WW;
        const float* row1 = sL + r1 * WW;
        const float A = w0 * row0[cm1]   + w1 * row1[cm1];
        const float B = w0 * row0[c]     + w1 * row1[c];
        const float C = w0 * row0[c + 1] + w1 * row1[c + 1];

        float4 v;
        v.x = (ox4 == 0) ? B : 0.5f * (A + B);
        v.y = B;
        v.z = 0.5f * (B + C);
        v.w = C;

        v.x = 1.0f / (1.0f + __expf(-v.x));
        v.y = 1.0f / (1.0f + __expf(-v.y));
        v.z = 1.0f / (1.0f + __expf(-v.z));
        v.w = 1.0f / (1.0f + __expf(-v.w));

        *reinterpret_cast<float4*>(ob + oy * OWw + ox4) = v;
    }
}

extern "C" void kernel_launch(void* const* d_in, const int* in_sizes, int n_in,
                              void* d_out, int out_size)
{
    const float* feats = (const float*)d_in[0];
    const float* p1    = (const float*)d_in[1];
    const float* p2    = (const float*)d_in[2];
    const float* loc   = (const float*)d_in[3];
    const float* off   = (const float*)d_in[4];
    const int*   imi   = (const int*)  d_in[5];
    const int*   fpn   = (const int*)  d_in[6];
    float* out = (float*)d_out;

    const int n_inst = in_sizes[5];                 // im_inds count = 200
    const size_t smem_bytes = (size_t)(HW + NP) * sizeof(float);  // 62116 B

    static bool attr_set = false;
    if (!attr_set) {
        cudaFuncSetAttribute(dmh_kernel,
                             cudaFuncAttributeMaxDynamicSharedMemorySize,
                             (int)smem_bytes);
        attr_set = true;
    }

    dim3 grid(n_inst, 2);
    dmh_kernel<<<grid, NTHREADS, smem_bytes>>>(feats, p1, p2, loc, off, imi, fpn, out);
}